// round 13
// baseline (speedup 1.0000x reference)
#include <cuda_runtime.h>
#include <cuda_fp16.h>
#include <cstdint>
#include <cstddef>

// ---------------------------------------------------------------------------
// out[e] = relu(x[src]@W1[:D] + x[tar]@W1[D:] + b1) @ W2 + b2
// Stage 1: P[n] = [x[n]@W1a + b1 | x[n]@W1b] via mma.sync tf32 + cp.async,
//          stored as fp16 (halves gather traffic; P fits in L2).
// Stage 2: per-edge gather + relu-dot, 8 edges per warp (half-warp per edge).
// ---------------------------------------------------------------------------

#define D_DIM  128
#define N_COLS 256
#define N_MAX  100000

__device__ __half g_Ph[(size_t)N_MAX * N_COLS];  // ~51.2 MB (fits L2)
__device__ float  g_Bt[N_COLS * D_DIM];          // B[n][k], tf32-rounded, K-major
__device__ int    g_idx32;

// ------------------------------ helpers ------------------------------------
__device__ __forceinline__ uint32_t smem_u32(const void* p) {
    uint32_t a;
    asm("{ .reg .u64 t; cvta.to.shared.u64 t, %1; cvt.u32.u64 %0, t; }"
        : "=r"(a) : "l"(p));
    return a;
}
__device__ __forceinline__ uint32_t to_tf32(float f) {
    uint32_t r;
    asm("cvt.rna.tf32.f32 %0, %1;" : "=r"(r) : "f"(f));
    return r;
}
__device__ __forceinline__ void ldsm_x4(uint32_t& r0, uint32_t& r1,
                                        uint32_t& r2, uint32_t& r3, uint32_t addr) {
    asm volatile("ldmatrix.sync.aligned.m8n8.x4.shared.b16 {%0,%1,%2,%3}, [%4];"
                 : "=r"(r0), "=r"(r1), "=r"(r2), "=r"(r3) : "r"(addr));
}
__device__ __forceinline__ void mma_tf32(float& c0, float& c1, float& c2, float& c3,
                                         uint32_t a0, uint32_t a1, uint32_t a2, uint32_t a3,
                                         uint32_t b0, uint32_t b1) {
    asm volatile(
        "mma.sync.aligned.m16n8k8.row.col.f32.tf32.tf32.f32 "
        "{%0,%1,%2,%3}, {%4,%5,%6,%7}, {%8,%9}, {%0,%1,%2,%3};"
        : "+f"(c0), "+f"(c1), "+f"(c2), "+f"(c3)
        : "r"(a0), "r"(a1), "r"(a2), "r"(a3), "r"(b0), "r"(b1));
}
__device__ __forceinline__ uint32_t swz(uint32_t byte) {   // SW128: Swizzle<3,4,3>
    return byte ^ ((byte >> 3) & 0x70u);
}
__device__ __forceinline__ void cp16(uint32_t dst, const void* src, int nbytes) {
    asm volatile("cp.async.cg.shared.global [%0], [%1], 16, %2;"
                 :: "r"(dst), "l"(__cvta_generic_to_global(src)), "r"(nbytes));
}
#define CP_COMMIT() asm volatile("cp.async.commit_group;" ::: "memory")
#define CP_WAIT0()  asm volatile("cp.async.wait_group 0;" ::: "memory")

// ---------------------------------------------------------------------------
// index dtype detection (int32 vs int64 on disk)
// ---------------------------------------------------------------------------
__global__ void detect_idx_kernel(const long long* __restrict__ pos) {
    if (threadIdx.x == 0) {
        int is32 = 0;
        #pragma unroll
        for (int i = 0; i < 16; ++i)
            if ((unsigned long long)pos[i] > 0xFFFFFFFFull) is32 = 1;
        g_idx32 = is32;
    }
}

// ---------------------------------------------------------------------------
// Build B[n][k] (tf32-rounded) from W1 [256,128] row-major
// ---------------------------------------------------------------------------
__global__ void prep_w_kernel(const float* __restrict__ W1) {
    int i = blockIdx.x * blockDim.x + threadIdx.x;
    if (i < N_COLS * D_DIM) {
        int n = i / D_DIM, k = i % D_DIM;
        float v = (n < D_DIM) ? W1[k * D_DIM + n]
                              : W1[(D_DIM + k) * D_DIM + (n - D_DIM)];
        g_Bt[i] = __uint_as_float(to_tf32(v));
    }
}

// ---------------------------------------------------------------------------
// tf32 mma.sync GEMM, cp.async double-buffered, fp16 output:
// Ph[M,256] = fp16(X[M,128] @ B^T (+ b1 on cols 0..127))
// BM=128, BN=128, BK=32 (4 stages), 256 threads = 8 warps (4m x 2n).
// grid = (ceil(M/128), 2)
// ---------------------------------------------------------------------------
#define SA_OFF(b) ((b) * 16384)
#define SB_OFF(b) (32768 + (b) * 16384)
#define GEMM_SMEM (65536 + 1024)

__global__ __launch_bounds__(256, 2)
void gemm_mma_kernel(const float* __restrict__ X, const float* __restrict__ b1, int M) {
    extern __shared__ char smem_raw[];
    const uint32_t sb = (smem_u32(smem_raw) + 1023u) & ~1023u;

    const int tid    = threadIdx.x;
    const int lane   = tid & 31;
    const int wid    = tid >> 5;
    const int warp_m = wid >> 1;
    const int warp_n = wid & 1;
    const int m0     = blockIdx.x * 128;
    const int nhalf  = blockIdx.y;

    float acc[2][8][4];
    #pragma unroll
    for (int i = 0; i < 2; ++i)
        #pragma unroll
        for (int j = 0; j < 8; ++j)
            #pragma unroll
            for (int c = 0; c < 4; ++c) acc[i][j][c] = 0.f;

    const int st_row0 = tid >> 3;
    const int st_c4   = tid & 7;

    const int a_mrow  = warp_m * 32 + (lane & 15);
    const int a_khalf = lane >> 4;
    const int b_nrow  = warp_n * 64 + ((lane >> 4) << 3) + (lane & 7);
    const int b_khalf = (lane >> 3) & 1;

#define STAGE(k0, bsel) do {                                                   \
    _Pragma("unroll")                                                          \
    for (int i = 0; i < 4; ++i) {                                              \
        int row = st_row0 + i * 32;                                            \
        uint32_t off = swz((uint32_t)(row << 7) + (uint32_t)(st_c4 << 4));     \
        int gr = m0 + row;                                                     \
        const float* srcA = X + (size_t)(gr < M ? gr : 0) * D_DIM + (k0) + st_c4 * 4; \
        cp16(sb + SA_OFF(bsel) + off, srcA, gr < M ? 16 : 0);                  \
        const float* srcB = g_Bt + (size_t)(nhalf * 128 + row) * D_DIM + (k0) + st_c4 * 4; \
        cp16(sb + SB_OFF(bsel) + off, srcB, 16);                               \
    }                                                                          \
    CP_COMMIT();                                                               \
} while (0)

    STAGE(0, 0);
    int buf = 0;

    #pragma unroll
    for (int s = 0; s < 4; ++s) {
        CP_WAIT0();
        __syncthreads();
        if (s < 3) STAGE((s + 1) * 32, buf ^ 1);

        const uint32_t bA = sb + SA_OFF(buf);
        const uint32_t bB = sb + SB_OFF(buf);

        #pragma unroll
        for (int ks = 0; ks < 4; ++ks) {
            uint32_t a[2][4], b[4][4];
            #pragma unroll
            for (int am = 0; am < 2; ++am) {
                uint32_t byte = ((uint32_t)(a_mrow + am * 16) << 7)
                              + ((uint32_t)(ks * 2 + a_khalf) << 4);
                ldsm_x4(a[am][0], a[am][1], a[am][2], a[am][3], bA + swz(byte));
                #pragma unroll
                for (int j = 0; j < 4; ++j)
                    a[am][j] = to_tf32(__uint_as_float(a[am][j]));
            }
            #pragma unroll
            for (int bn = 0; bn < 4; ++bn) {
                uint32_t byte = ((uint32_t)(b_nrow + bn * 16) << 7)
                              + ((uint32_t)(ks * 2 + b_khalf) << 4);
                ldsm_x4(b[bn][0], b[bn][1], b[bn][2], b[bn][3], bB + swz(byte));
            }
            #pragma unroll
            for (int am = 0; am < 2; ++am)
                #pragma unroll
                for (int na = 0; na < 8; ++na) {
                    uint32_t b0  = b[na >> 1][(na & 1) * 2];
                    uint32_t b1r = b[na >> 1][(na & 1) * 2 + 1];
                    mma_tf32(acc[am][na][0], acc[am][na][1], acc[am][na][2], acc[am][na][3],
                             a[am][0], a[am][1], a[am][2], a[am][3], b0, b1r);
                }
        }
        __syncthreads();
        buf ^= 1;
    }
#undef STAGE

    // ---- epilogue: fp16 pack + store (half2 per c-frag pair), + b1 on half 0
    const int g  = lane >> 2;
    const int tq = lane & 3;
    float2 bias[8];
    #pragma unroll
    for (int na = 0; na < 8; ++na) {
        if (nhalf == 0) {
            bias[na] = *(const float2*)(b1 + warp_n * 64 + na * 8 + tq * 2);
        } else {
            bias[na] = make_float2(0.f, 0.f);
        }
    }
    #pragma unroll
    for (int am = 0; am < 2; ++am) {
        int r0 = m0 + warp_m * 32 + am * 16 + g;
        int r1 = r0 + 8;
        #pragma unroll
        for (int na = 0; na < 8; ++na) {
            int col = nhalf * 128 + warp_n * 64 + na * 8 + tq * 2;
            if (r0 < M)
                *(__half2*)(g_Ph + (size_t)r0 * N_COLS + col) =
                    __floats2half2_rn(acc[am][na][0] + bias[na].x,
                                      acc[am][na][1] + bias[na].y);
            if (r1 < M)
                *(__half2*)(g_Ph + (size_t)r1 * N_COLS + col) =
                    __floats2half2_rn(acc[am][na][2] + bias[na].x,
                                      acc[am][na][3] + bias[na].y);
        }
    }
}

// ---------------------------------------------------------------------------
// Edge kernel: 8 edges per warp; each half-warp (16 lanes) handles 4 edges.
// Row = 128 fp16 = 256 B = 16 lanes x uint4 (LDG.128 preserved).
// out[e] = sum_d relu(Ph[src][d] + Ph[tar][128+d]) * W2[d] + b2
// ---------------------------------------------------------------------------
__global__ __launch_bounds__(256)
void edge_kernel(const long long* __restrict__ pos,
                 const long long* __restrict__ neg,
                 const float* __restrict__ W2,
                 const float* __restrict__ b2,
                 float* __restrict__ out,
                 int Epos, int Eneg) {
    const int warp = (blockIdx.x * blockDim.x + threadIdx.x) >> 5;
    const int lane = threadIdx.x & 31;
    const int half = lane >> 4;
    const int hl   = lane & 15;
    const int Etot = Epos + Eneg;
    const int e0   = warp * 8 + half * 4;      // this half-warp's 4 edges
    if (warp * 8 >= Etot) return;

    const int idx32 = g_idx32;

    long long sidx[4], tidx[4];
    #pragma unroll
    for (int j = 0; j < 4; ++j) {
        int e = e0 + j;
        if (e >= Etot) { sidx[j] = 0; tidx[j] = 0; continue; }
        if (idx32) {
            if (e < Epos) {
                const int* p = (const int*)pos;
                sidx[j] = p[e];          tidx[j] = p[Epos + e];
            } else {
                const int* p = (const int*)neg;
                int q = e - Epos;
                sidx[j] = p[q];          tidx[j] = p[Eneg + q];
            }
        } else {
            if (e < Epos) { sidx[j] = pos[e];        tidx[j] = pos[Epos + e]; }
            else          { int q = e - Epos;
                            sidx[j] = neg[q];        tidx[j] = neg[Eneg + q]; }
        }
    }

    const float4 w0 = *(const float4*)(W2 + hl * 8);
    const float4 w1 = *(const float4*)(W2 + hl * 8 + 4);

    uint4 av[4], bv[4];
    #pragma unroll
    for (int j = 0; j < 4; ++j) {
        av[j] = *(const uint4*)(g_Ph + (size_t)sidx[j] * N_COLS + hl * 8);
        bv[j] = *(const uint4*)(g_Ph + (size_t)tidx[j] * N_COLS + D_DIM + hl * 8);
    }

    float s[4];
    #pragma unroll
    for (int j = 0; j < 4; ++j) {
        float2 a0 = __half22float2(*(const __half2*)&av[j].x);
        float2 a1 = __half22float2(*(const __half2*)&av[j].y);
        float2 a2 = __half22float2(*(const __half2*)&av[j].z);
        float2 a3 = __half22float2(*(const __half2*)&av[j].w);
        float2 c0 = __half22float2(*(const __half2*)&bv[j].x);
        float2 c1 = __half22float2(*(const __half2*)&bv[j].y);
        float2 c2 = __half22float2(*(const __half2*)&bv[j].z);
        float2 c3 = __half22float2(*(const __half2*)&bv[j].w);
        s[j] = fmaxf(a0.x + c0.x, 0.f) * w0.x
             + fmaxf(a0.y + c0.y, 0.f) * w0.y
             + fmaxf(a1.x + c1.x, 0.f) * w0.z
             + fmaxf(a1.y + c1.y, 0.f) * w0.w
             + fmaxf(a2.x + c2.x, 0.f) * w1.x
             + fmaxf(a2.y + c2.y, 0.f) * w1.y
             + fmaxf(a3.x + c3.x, 0.f) * w1.z
             + fmaxf(a3.y + c3.y, 0.f) * w1.w;
    }

    #pragma unroll
    for (int off = 8; off; off >>= 1) {        // reduce within half-warp
        #pragma unroll
        for (int j = 0; j < 4; ++j)
            s[j] += __shfl_xor_sync(0xffffffffu, s[j], off);
    }

    if (hl == 0) {
        const float bb = b2[0];
        #pragma unroll
        for (int j = 0; j < 4; ++j)
            if (e0 + j < Etot) out[e0 + j] = s[j] + bb;
    }
}

// ---------------------------------------------------------------------------
extern "C" void kernel_launch(void* const* d_in, const int* in_sizes, int n_in,
                              void* d_out, int out_size) {
    const float* x   = (const float*)d_in[0];
    const void*  pos = d_in[1];
    const void*  neg = d_in[2];
    const float* W1  = (const float*)d_in[3];
    const float* b1  = (const float*)d_in[4];
    const float* W2  = (const float*)d_in[5];
    const float* b2  = (const float*)d_in[6];
    float* out = (float*)d_out;

    const int M    = in_sizes[0] / D_DIM;
    const int Epos = in_sizes[1] / 2;
    const int Eneg = in_sizes[2] / 2;
    const int Etot = Epos + Eneg;
    const int ntiles = (M + 127) / 128;

    static bool attr_set = false;
    if (!attr_set) {
        cudaFuncSetAttribute(gemm_mma_kernel,
                             cudaFuncAttributeMaxDynamicSharedMemorySize, GEMM_SMEM);
        attr_set = true;
    }

    detect_idx_kernel<<<1, 32>>>((const long long*)pos);
    prep_w_kernel<<<(N_COLS * D_DIM + 255) / 256, 256>>>(W1);

    dim3 gg((unsigned)ntiles, 2);
    gemm_mma_kernel<<<gg, 256, GEMM_SMEM>>>(x, b1, M);

    int warps = (Etot + 7) / 8;
    unsigned eblocks = (unsigned)((warps + 7) / 8);     // 8 warps / 256-thr block
    edge_kernel<<<eblocks, 256>>>((const long long*)pos, (const long long*)neg,
                                  W2, b2, out, Epos, Eneg);
}

// round 14
// speedup vs baseline: 1.6094x; 1.6094x over previous
#include <cuda_runtime.h>
#include <cuda_fp16.h>
#include <cstdint>
#include <cstddef>

// ---------------------------------------------------------------------------
// out[e] = relu(x[src]@W1[:D] + x[tar]@W1[D:] + b1) @ W2 + b2
// Stage 1: P[n] = [x[n]@W1a + b1 | x[n]@W1b] via mma.sync tf32 + cp.async,
//          stored fp16 in a per-64-block PERMUTED column order so the c-frag
//          epilogue stores coalesced uint4s.  W2 permuted identically -> the
//          edge dot product is invariant.
// Stage 2: per-edge gather + relu-dot, 8 edges/warp, half2 add+relu.
// ---------------------------------------------------------------------------

#define D_DIM  128
#define N_COLS 256
#define N_MAX  100000

__device__ __half g_Ph[(size_t)N_MAX * N_COLS];  // ~51.2 MB (L2-resident)
__device__ float  g_Bt[N_COLS * D_DIM];          // B[n][k], tf32-rounded, K-major
__device__ float  g_W2p[D_DIM];                  // W2 in permuted column order
__device__ int    g_idx32;

// ------------------------------ helpers ------------------------------------
__device__ __forceinline__ uint32_t smem_u32(const void* p) {
    uint32_t a;
    asm("{ .reg .u64 t; cvta.to.shared.u64 t, %1; cvt.u32.u64 %0, t; }"
        : "=r"(a) : "l"(p));
    return a;
}
__device__ __forceinline__ uint32_t to_tf32(float f) {
    uint32_t r;
    asm("cvt.rna.tf32.f32 %0, %1;" : "=r"(r) : "f"(f));
    return r;
}
__device__ __forceinline__ void ldsm_x4(uint32_t& r0, uint32_t& r1,
                                        uint32_t& r2, uint32_t& r3, uint32_t addr) {
    asm volatile("ldmatrix.sync.aligned.m8n8.x4.shared.b16 {%0,%1,%2,%3}, [%4];"
                 : "=r"(r0), "=r"(r1), "=r"(r2), "=r"(r3) : "r"(addr));
}
__device__ __forceinline__ void mma_tf32(float& c0, float& c1, float& c2, float& c3,
                                         uint32_t a0, uint32_t a1, uint32_t a2, uint32_t a3,
                                         uint32_t b0, uint32_t b1) {
    asm volatile(
        "mma.sync.aligned.m16n8k8.row.col.f32.tf32.tf32.f32 "
        "{%0,%1,%2,%3}, {%4,%5,%6,%7}, {%8,%9}, {%0,%1,%2,%3};"
        : "+f"(c0), "+f"(c1), "+f"(c2), "+f"(c3)
        : "r"(a0), "r"(a1), "r"(a2), "r"(a3), "r"(b0), "r"(b1));
}
__device__ __forceinline__ uint32_t swz(uint32_t byte) {   // SW128: Swizzle<3,4,3>
    return byte ^ ((byte >> 3) & 0x70u);
}
__device__ __forceinline__ void cp16(uint32_t dst, const void* src, int nbytes) {
    asm volatile("cp.async.cg.shared.global [%0], [%1], 16, %2;"
                 :: "r"(dst), "l"(__cvta_generic_to_global(src)), "r"(nbytes));
}
#define CP_COMMIT() asm volatile("cp.async.commit_group;" ::: "memory")
#define CP_WAIT0()  asm volatile("cp.async.wait_group 0;" ::: "memory")

// ---------------------------------------------------------------------------
// index dtype detection (int32 vs int64 on disk)
// ---------------------------------------------------------------------------
__global__ void detect_idx_kernel(const long long* __restrict__ pos) {
    if (threadIdx.x == 0) {
        int is32 = 0;
        #pragma unroll
        for (int i = 0; i < 16; ++i)
            if ((unsigned long long)pos[i] > 0xFFFFFFFFull) is32 = 1;
        g_idx32 = is32;
    }
}

// ---------------------------------------------------------------------------
// Build B[n][k] (tf32-rounded) from W1, and permuted W2.
// Column permutation within each 64-block: o_src = na*8+tq*2+r -> o_dst =
// tq*16+na*2+r  (na<8, tq<4, r<2).
// ---------------------------------------------------------------------------
__global__ void prep_w_kernel(const float* __restrict__ W1,
                              const float* __restrict__ W2) {
    int i = blockIdx.x * blockDim.x + threadIdx.x;
    if (i < N_COLS * D_DIM) {
        int n = i / D_DIM, k = i % D_DIM;
        float v = (n < D_DIM) ? W1[k * D_DIM + n]
                              : W1[(D_DIM + k) * D_DIM + (n - D_DIM)];
        g_Bt[i] = __uint_as_float(to_tf32(v));
    }
    if (i < D_DIM) {   // i = permuted position; find source position
        int b = i >> 6, o = i & 63;
        int tq = o >> 4, na = (o & 15) >> 1, r = o & 1;
        g_W2p[i] = W2[b * 64 + na * 8 + tq * 2 + r];
    }
}

// ---------------------------------------------------------------------------
// tf32 mma.sync GEMM, cp.async double-buffered, permuted fp16 output.
// BM=128, BN=128, BK=32 (4 stages), 256 threads = 8 warps (4m x 2n).
// grid = (ceil(M/128), 2)
// ---------------------------------------------------------------------------
#define SA_OFF(b) ((b) * 16384)
#define SB_OFF(b) (32768 + (b) * 16384)
#define GEMM_SMEM (65536 + 1024)

__global__ __launch_bounds__(256, 2)
void gemm_mma_kernel(const float* __restrict__ X, const float* __restrict__ b1, int M) {
    extern __shared__ char smem_raw[];
    const uint32_t sb = (smem_u32(smem_raw) + 1023u) & ~1023u;

    const int tid    = threadIdx.x;
    const int lane   = tid & 31;
    const int wid    = tid >> 5;
    const int warp_m = wid >> 1;
    const int warp_n = wid & 1;
    const int m0     = blockIdx.x * 128;
    const int nhalf  = blockIdx.y;

    float acc[2][8][4];
    #pragma unroll
    for (int i = 0; i < 2; ++i)
        #pragma unroll
        for (int j = 0; j < 8; ++j)
            #pragma unroll
            for (int c = 0; c < 4; ++c) acc[i][j][c] = 0.f;

    const int st_row0 = tid >> 3;
    const int st_c4   = tid & 7;

    const int a_mrow  = warp_m * 32 + (lane & 15);
    const int a_khalf = lane >> 4;
    const int b_nrow  = warp_n * 64 + ((lane >> 4) << 3) + (lane & 7);
    const int b_khalf = (lane >> 3) & 1;

#define STAGE(k0, bsel) do {                                                   \
    _Pragma("unroll")                                                          \
    for (int i = 0; i < 4; ++i) {                                              \
        int row = st_row0 + i * 32;                                            \
        uint32_t off = swz((uint32_t)(row << 7) + (uint32_t)(st_c4 << 4));     \
        int gr = m0 + row;                                                     \
        const float* srcA = X + (size_t)(gr < M ? gr : 0) * D_DIM + (k0) + st_c4 * 4; \
        cp16(sb + SA_OFF(bsel) + off, srcA, gr < M ? 16 : 0);                  \
        const float* srcB = g_Bt + (size_t)(nhalf * 128 + row) * D_DIM + (k0) + st_c4 * 4; \
        cp16(sb + SB_OFF(bsel) + off, srcB, 16);                               \
    }                                                                          \
    CP_COMMIT();                                                               \
} while (0)

    STAGE(0, 0);
    int buf = 0;

    #pragma unroll
    for (int s = 0; s < 4; ++s) {
        CP_WAIT0();
        __syncthreads();
        if (s < 3) STAGE((s + 1) * 32, buf ^ 1);

        const uint32_t bA = sb + SA_OFF(buf);
        const uint32_t bB = sb + SB_OFF(buf);

        #pragma unroll
        for (int ks = 0; ks < 4; ++ks) {
            uint32_t a[2][4], b[4][4];
            #pragma unroll
            for (int am = 0; am < 2; ++am) {
                uint32_t byte = ((uint32_t)(a_mrow + am * 16) << 7)
                              + ((uint32_t)(ks * 2 + a_khalf) << 4);
                ldsm_x4(a[am][0], a[am][1], a[am][2], a[am][3], bA + swz(byte));
                #pragma unroll
                for (int j = 0; j < 4; ++j)
                    a[am][j] = to_tf32(__uint_as_float(a[am][j]));
            }
            #pragma unroll
            for (int bn = 0; bn < 4; ++bn) {
                uint32_t byte = ((uint32_t)(b_nrow + bn * 16) << 7)
                              + ((uint32_t)(ks * 2 + b_khalf) << 4);
                ldsm_x4(b[bn][0], b[bn][1], b[bn][2], b[bn][3], bB + swz(byte));
            }
            #pragma unroll
            for (int am = 0; am < 2; ++am)
                #pragma unroll
                for (int na = 0; na < 8; ++na) {
                    uint32_t b0  = b[na >> 1][(na & 1) * 2];
                    uint32_t b1r = b[na >> 1][(na & 1) * 2 + 1];
                    mma_tf32(acc[am][na][0], acc[am][na][1], acc[am][na][2], acc[am][na][3],
                             a[am][0], a[am][1], a[am][2], a[am][3], b0, b1r);
                }
        }
        __syncthreads();
        buf ^= 1;
    }
#undef STAGE

    // ---- epilogue: permuted layout -> each thread owns 16 contiguous fp16
    //      per row (cols' [tq*16, tq*16+16) of its warp_n 64-block).
    const int g  = lane >> 2;
    const int tq = lane & 3;
    float2 bias[8];
    #pragma unroll
    for (int na = 0; na < 8; ++na) {
        if (nhalf == 0) {
            bias[na] = *(const float2*)(b1 + warp_n * 64 + na * 8 + tq * 2);
        } else {
            bias[na] = make_float2(0.f, 0.f);
        }
    }
    const int colbase = nhalf * 128 + warp_n * 64 + tq * 16;
    #pragma unroll
    for (int am = 0; am < 2; ++am) {
        #pragma unroll
        for (int h = 0; h < 2; ++h) {              // row pair r0 / r0+8
            int row = m0 + warp_m * 32 + am * 16 + h * 8 + g;
            if (row < M) {
                __half2 h2[8];
                #pragma unroll
                for (int na = 0; na < 8; ++na)
                    h2[na] = __floats2half2_rn(acc[am][na][2 * h] + bias[na].x,
                                               acc[am][na][2 * h + 1] + bias[na].y);
                __half* dst = g_Ph + (size_t)row * N_COLS + colbase;
                *(uint4*)(dst)     = *(const uint4*)&h2[0];
                *(uint4*)(dst + 8) = *(const uint4*)&h2[4];
            }
        }
    }
}

// ---------------------------------------------------------------------------
// Edge kernel: 8 edges per warp; half-warp (16 lanes) per 4 edges.
// half2 add+relu, fp32 cvt+FMA dot, 32-bit byte offsets into g_Ph.
// ---------------------------------------------------------------------------
__global__ __launch_bounds__(256)
void edge_kernel(const long long* __restrict__ pos,
                 const long long* __restrict__ neg,
                 const float* __restrict__ b2,
                 float* __restrict__ out,
                 int Epos, int Eneg) {
    const int warp = (blockIdx.x * blockDim.x + threadIdx.x) >> 5;
    const int lane = threadIdx.x & 31;
    const int half = lane >> 4;
    const int hl   = lane & 15;
    const int Etot = Epos + Eneg;
    const int e0   = warp * 8 + half * 4;
    if (warp * 8 >= Etot) return;

    const int idx32 = g_idx32;

    uint32_t soff[4], toff[4];
    #pragma unroll
    for (int j = 0; j < 4; ++j) {
        int e = e0 + j;
        long long s = 0, t = 0;
        if (e < Etot) {
            if (idx32) {
                if (e < Epos) {
                    const int* p = (const int*)pos;
                    s = p[e];          t = p[Epos + e];
                } else {
                    const int* p = (const int*)neg;
                    int q = e - Epos;
                    s = p[q];          t = p[Eneg + q];
                }
            } else {
                if (e < Epos) { s = pos[e];        t = pos[Epos + e]; }
                else          { int q = e - Epos;
                                s = neg[q];        t = neg[Eneg + q]; }
            }
        }
        soff[j] = (uint32_t)s << 9;                 // *256 cols *2 B
        toff[j] = ((uint32_t)t << 9) + 256u;        // + D_DIM*2 B
    }

    const char* Pb = (const char*)g_Ph;
    const uint32_t lb = (uint32_t)hl << 4;          // 16 B per lane

    const float4 w0 = *(const float4*)(g_W2p + hl * 8);
    const float4 w1 = *(const float4*)(g_W2p + hl * 8 + 4);

    uint4 av[4], bv[4];
    #pragma unroll
    for (int j = 0; j < 4; ++j) {
        av[j] = *(const uint4*)(Pb + soff[j] + lb);
        bv[j] = *(const uint4*)(Pb + toff[j] + lb);
    }

    const __half2 z = __float2half2_rn(0.f);
    float s[4];
    #pragma unroll
    for (int j = 0; j < 4; ++j) {
        __half2 h0 = __hmax2(__hadd2(*(const __half2*)&av[j].x, *(const __half2*)&bv[j].x), z);
        __half2 h1 = __hmax2(__hadd2(*(const __half2*)&av[j].y, *(const __half2*)&bv[j].y), z);
        __half2 h2 = __hmax2(__hadd2(*(const __half2*)&av[j].z, *(const __half2*)&bv[j].z), z);
        __half2 h3 = __hmax2(__hadd2(*(const __half2*)&av[j].w, *(const __half2*)&bv[j].w), z);
        float2 f0 = __half22float2(h0);
        float2 f1 = __half22float2(h1);
        float2 f2 = __half22float2(h2);
        float2 f3 = __half22float2(h3);
        float r = f0.x * w0.x;
        r = fmaf(f0.y, w0.y, r);
        r = fmaf(f1.x, w0.z, r);
        r = fmaf(f1.y, w0.w, r);
        r = fmaf(f2.x, w1.x, r);
        r = fmaf(f2.y, w1.y, r);
        r = fmaf(f3.x, w1.z, r);
        r = fmaf(f3.y, w1.w, r);
        s[j] = r;
    }

    #pragma unroll
    for (int off = 8; off; off >>= 1) {
        #pragma unroll
        for (int j = 0; j < 4; ++j)
            s[j] += __shfl_xor_sync(0xffffffffu, s[j], off);
    }

    if (hl == 0) {
        const float bb = b2[0];
        #pragma unroll
        for (int j = 0; j < 4; ++j)
            if (e0 + j < Etot) out[e0 + j] = s[j] + bb;
    }
}

// ---------------------------------------------------------------------------
extern "C" void kernel_launch(void* const* d_in, const int* in_sizes, int n_in,
                              void* d_out, int out_size) {
    const float* x   = (const float*)d_in[0];
    const void*  pos = d_in[1];
    const void*  neg = d_in[2];
    const float* W1  = (const float*)d_in[3];
    const float* b1  = (const float*)d_in[4];
    const float* W2  = (const float*)d_in[5];
    const float* b2  = (const float*)d_in[6];
    float* out = (float*)d_out;

    const int M    = in_sizes[0] / D_DIM;
    const int Epos = in_sizes[1] / 2;
    const int Eneg = in_sizes[2] / 2;
    const int Etot = Epos + Eneg;
    const int ntiles = (M + 127) / 128;

    static bool attr_set = false;
    if (!attr_set) {
        cudaFuncSetAttribute(gemm_mma_kernel,
                             cudaFuncAttributeMaxDynamicSharedMemorySize, GEMM_SMEM);
        attr_set = true;
    }

    detect_idx_kernel<<<1, 32>>>((const long long*)pos);
    prep_w_kernel<<<(N_COLS * D_DIM + 255) / 256, 256>>>(W1, W2);

    dim3 gg((unsigned)ntiles, 2);
    gemm_mma_kernel<<<gg, 256, GEMM_SMEM>>>(x, b1, M);

    int warps = (Etot + 7) / 8;
    unsigned eblocks = (unsigned)((warps + 7) / 8);
    edge_kernel<<<eblocks, 256>>>((const long long*)pos, (const long long*)neg,
                                  b2, out, Epos, Eneg);
}

// round 16
// speedup vs baseline: 1.6849x; 1.0469x over previous
#include <cuda_runtime.h>
#include <cuda_fp16.h>
#include <cstdint>
#include <cstddef>

// ---------------------------------------------------------------------------
// out[e] = relu(x[src]@W1[:D] + x[tar]@W1[D:] + b1) @ W2 + b2
// Stage 0: convert X -> fp16 (g_Xh), W1 -> rearranged fp16 B (g_Bh).
// Stage 1: Ph[n] = fp16(x[n]@W1a + b1 | x[n]@W1b) via mma.sync m16n8k16.f16
//          (fp32 accum) + cp.async double buffering.  Ph stored in permuted
//          column order (coalesced epilogue); W2 permuted identically.
// Stage 2: per-edge gather + relu-dot, 8 edges/warp, half2 math.
// ---------------------------------------------------------------------------

#define D_DIM  128
#define N_COLS 256
#define N_MAX  100000

__device__ __half g_Ph[(size_t)N_MAX * N_COLS];  // ~51.2 MB (L2-resident)
__device__ __half g_Xh[(size_t)N_MAX * D_DIM];   // ~25.6 MB fp16 copy of X
__device__ __half g_Bh[N_COLS * D_DIM];          // B[n][k] fp16, K-major
__device__ float  g_W2p[D_DIM];                  // W2 in permuted column order
__device__ int    g_idx32;

// ------------------------------ helpers ------------------------------------
__device__ __forceinline__ uint32_t smem_u32(const void* p) {
    uint32_t a;
    asm("{ .reg .u64 t; cvta.to.shared.u64 t, %1; cvt.u32.u64 %0, t; }"
        : "=r"(a) : "l"(p));
    return a;
}
__device__ __forceinline__ void ldsm_x4(uint32_t& r0, uint32_t& r1,
                                        uint32_t& r2, uint32_t& r3, uint32_t addr) {
    asm volatile("ldmatrix.sync.aligned.m8n8.x4.shared.b16 {%0,%1,%2,%3}, [%4];"
                 : "=r"(r0), "=r"(r1), "=r"(r2), "=r"(r3) : "r"(addr));
}
__device__ __forceinline__ void mma_f16(float& c0, float& c1, float& c2, float& c3,
                                        uint32_t a0, uint32_t a1, uint32_t a2, uint32_t a3,
                                        uint32_t b0, uint32_t b1) {
    asm volatile(
        "mma.sync.aligned.m16n8k16.row.col.f32.f16.f16.f32 "
        "{%0,%1,%2,%3}, {%4,%5,%6,%7}, {%8,%9}, {%0,%1,%2,%3};"
        : "+f"(c0), "+f"(c1), "+f"(c2), "+f"(c3)
        : "r"(a0), "r"(a1), "r"(a2), "r"(a3), "r"(b0), "r"(b1));
}
__device__ __forceinline__ uint32_t swz(uint32_t byte) {   // SW128: Swizzle<3,4,3>
    return byte ^ ((byte >> 3) & 0x70u);
}
__device__ __forceinline__ void cp16(uint32_t dst, const void* src, int nbytes) {
    asm volatile("cp.async.cg.shared.global [%0], [%1], 16, %2;"
                 :: "r"(dst), "l"(__cvta_generic_to_global(src)), "r"(nbytes));
}
#define CP_COMMIT() asm volatile("cp.async.commit_group;" ::: "memory")
#define CP_WAIT0()  asm volatile("cp.async.wait_group 0;" ::: "memory")

// ---------------------------------------------------------------------------
// index dtype detection (int32 vs int64 on disk)
// ---------------------------------------------------------------------------
__global__ void detect_idx_kernel(const long long* __restrict__ pos) {
    if (threadIdx.x == 0) {
        int is32 = 0;
        #pragma unroll
        for (int i = 0; i < 16; ++i)
            if ((unsigned long long)pos[i] > 0xFFFFFFFFull) is32 = 1;
        g_idx32 = is32;
    }
}

// ---------------------------------------------------------------------------
// X -> fp16 (8 elems per thread, 32B read / 16B write)
// ---------------------------------------------------------------------------
__global__ void prep_x_kernel(const float* __restrict__ X, int total8) {
    int i = blockIdx.x * blockDim.x + threadIdx.x;
    if (i < total8) {
        const float4 v0 = *(const float4*)(X + (size_t)i * 8);
        const float4 v1 = *(const float4*)(X + (size_t)i * 8 + 4);
        __half2 h[4];
        h[0] = __floats2half2_rn(v0.x, v0.y);
        h[1] = __floats2half2_rn(v0.z, v0.w);
        h[2] = __floats2half2_rn(v1.x, v1.y);
        h[3] = __floats2half2_rn(v1.z, v1.w);
        *(uint4*)(g_Xh + (size_t)i * 8) = *(const uint4*)h;
    }
}

// ---------------------------------------------------------------------------
// Build B[n][k] fp16 from W1, and permuted W2.
//   n<128:  B[n][k] = W1[k][n];  n>=128: B[n][k] = W1[128+k][n-128]
// Column permutation per 64-block: src na*8+tq*2+r -> dst tq*16+na*2+r.
// ---------------------------------------------------------------------------
__global__ void prep_w_kernel(const float* __restrict__ W1,
                              const float* __restrict__ W2) {
    int i = blockIdx.x * blockDim.x + threadIdx.x;
    if (i < N_COLS * D_DIM) {
        int n = i / D_DIM, k = i % D_DIM;
        float v = (n < D_DIM) ? W1[k * D_DIM + n]
                              : W1[(D_DIM + k) * D_DIM + (n - D_DIM)];
        g_Bh[i] = __float2half_rn(v);
    }
    if (i < D_DIM) {   // i = permuted position
        int b = i >> 6, o = i & 63;
        int tq = o >> 4, na = (o & 15) >> 1, r = o & 1;
        g_W2p[i] = W2[b * 64 + na * 8 + tq * 2 + r];
    }
}

// ---------------------------------------------------------------------------
// fp16 mma.sync GEMM, cp.async double-buffered, permuted fp16 output.
// BM=128, BN=128, BK=64 (2 stages), 256 threads = 8 warps (4m x 2n).
// Tiles: 128 rows x 128 B (64 fp16) SW128 -> 16 KB each, 2 buffers = 64 KB.
// grid = (ceil(M/128), 2)
// ---------------------------------------------------------------------------
#define SA_OFF(b) ((b) * 16384)
#define SB_OFF(b) (32768 + (b) * 16384)
#define GEMM_SMEM (65536 + 1024)

__global__ __launch_bounds__(256, 2)
void gemm_mma_kernel(const float* __restrict__ b1, int M) {
    extern __shared__ char smem_raw[];
    const uint32_t sb = (smem_u32(smem_raw) + 1023u) & ~1023u;

    const int tid    = threadIdx.x;
    const int lane   = tid & 31;
    const int wid    = tid >> 5;
    const int warp_m = wid >> 1;
    const int warp_n = wid & 1;
    const int m0     = blockIdx.x * 128;
    const int nhalf  = blockIdx.y;

    float acc[2][8][4];
    #pragma unroll
    for (int i = 0; i < 2; ++i)
        #pragma unroll
        for (int j = 0; j < 8; ++j)
            #pragma unroll
            for (int c = 0; c < 4; ++c) acc[i][j][c] = 0.f;

    // staging: 1024 16B cells per 16KB tile, 4 per thread; 8 cells per row
    const int st_row0 = tid >> 3;        // rows 0..31 (+32 per i)
    const int st_c    = tid & 7;         // cell within row (8 fp16 each)

    // ldmatrix lane->address components (rows are 128 B — same as tf32 ver)
    const int a_mrow  = warp_m * 32 + (lane & 15);
    const int a_khalf = lane >> 4;
    const int b_nrow  = warp_n * 64 + ((lane >> 4) << 3) + (lane & 7);
    const int b_khalf = (lane >> 3) & 1;

#define STAGE(k0, bsel) do {                                                   \
    _Pragma("unroll")                                                          \
    for (int i = 0; i < 4; ++i) {                                              \
        int row = st_row0 + i * 32;                                            \
        uint32_t off = swz((uint32_t)(row << 7) + (uint32_t)(st_c << 4));      \
        int gr = m0 + row;                                                     \
        const __half* srcA = g_Xh + (size_t)(gr < M ? gr : 0) * D_DIM + (k0) + st_c * 8; \
        cp16(sb + SA_OFF(bsel) + off, srcA, gr < M ? 16 : 0);                  \
        const __half* srcB = g_Bh + (size_t)(nhalf * 128 + row) * D_DIM + (k0) + st_c * 8; \
        cp16(sb + SB_OFF(bsel) + off, srcB, 16);                               \
    }                                                                          \
    CP_COMMIT();                                                               \
} while (0)

    STAGE(0, 0);
    int buf = 0;

    #pragma unroll
    for (int s = 0; s < 2; ++s) {
        CP_WAIT0();
        __syncthreads();
        if (s < 1) STAGE(64, 1);

        const uint32_t bA = sb + SA_OFF(buf);
        const uint32_t bB = sb + SB_OFF(buf);

        #pragma unroll
        for (int ks = 0; ks < 4; ++ks) {          // k16-steps within BK=64
            uint32_t a[2][4], b[4][4];
            #pragma unroll
            for (int am = 0; am < 2; ++am) {
                uint32_t byte = ((uint32_t)(a_mrow + am * 16) << 7)
                              + ((uint32_t)(ks * 2 + a_khalf) << 4);
                ldsm_x4(a[am][0], a[am][1], a[am][2], a[am][3], bA + swz(byte));
            }
            #pragma unroll
            for (int bn = 0; bn < 4; ++bn) {
                uint32_t byte = ((uint32_t)(b_nrow + bn * 16) << 7)
                              + ((uint32_t)(ks * 2 + b_khalf) << 4);
                ldsm_x4(b[bn][0], b[bn][1], b[bn][2], b[bn][3], bB + swz(byte));
            }
            #pragma unroll
            for (int am = 0; am < 2; ++am)
                #pragma unroll
                for (int na = 0; na < 8; ++na) {
                    uint32_t b0  = b[na >> 1][(na & 1) * 2];
                    uint32_t b1r = b[na >> 1][(na & 1) * 2 + 1];
                    mma_f16(acc[am][na][0], acc[am][na][1], acc[am][na][2], acc[am][na][3],
                            a[am][0], a[am][1], a[am][2], a[am][3], b0, b1r);
                }
        }
        __syncthreads();
        buf ^= 1;
    }
#undef STAGE

    // ---- epilogue: permuted layout -> 16 contiguous fp16 per thread-row
    const int g  = lane >> 2;
    const int tq = lane & 3;
    float2 bias[8];
    #pragma unroll
    for (int na = 0; na < 8; ++na) {
        if (nhalf == 0) {
            bias[na] = *(const float2*)(b1 + warp_n * 64 + na * 8 + tq * 2);
        } else {
            bias[na] = make_float2(0.f, 0.f);
        }
    }
    const int colbase = nhalf * 128 + warp_n * 64 + tq * 16;
    #pragma unroll
    for (int am = 0; am < 2; ++am) {
        #pragma unroll
        for (int h = 0; h < 2; ++h) {
            int row = m0 + warp_m * 32 + am * 16 + h * 8 + g;
            if (row < M) {
                __half2 h2[8];
                #pragma unroll
                for (int na = 0; na < 8; ++na)
                    h2[na] = __floats2half2_rn(acc[am][na][2 * h] + bias[na].x,
                                               acc[am][na][2 * h + 1] + bias[na].y);
                __half* dst = g_Ph + (size_t)row * N_COLS + colbase;
                *(uint4*)(dst)     = *(const uint4*)&h2[0];
                *(uint4*)(dst + 8) = *(const uint4*)&h2[4];
            }
        }
    }
}

// ---------------------------------------------------------------------------
// Edge kernel: 8 edges per warp; half-warp (16 lanes) per 4 edges.
// half2 add+relu, fp32 cvt+FMA dot, 32-bit byte offsets into g_Ph.
// ---------------------------------------------------------------------------
__global__ __launch_bounds__(256)
void edge_kernel(const long long* __restrict__ pos,
                 const long long* __restrict__ neg,
                 const float* __restrict__ b2,
                 float* __restrict__ out,
                 int Epos, int Eneg) {
    const int warp = (blockIdx.x * blockDim.x + threadIdx.x) >> 5;
    const int lane = threadIdx.x & 31;
    const int half = lane >> 4;
    const int hl   = lane & 15;
    const int Etot = Epos + Eneg;
    const int e0   = warp * 8 + half * 4;
    if (warp * 8 >= Etot) return;

    const int idx32 = g_idx32;

    uint32_t soff[4], toff[4];
    #pragma unroll
    for (int j = 0; j < 4; ++j) {
        int e = e0 + j;
        long long s = 0, t = 0;
        if (e < Etot) {
            if (idx32) {
                if (e < Epos) {
                    const int* p = (const int*)pos;
                    s = p[e];          t = p[Epos + e];
                } else {
                    const int* p = (const int*)neg;
                    int q = e - Epos;
                    s = p[q];          t = p[Eneg + q];
                }
            } else {
                if (e < Epos) { s = pos[e];        t = pos[Epos + e]; }
                else          { int q = e - Epos;
                                s = neg[q];        t = neg[Eneg + q]; }
            }
        }
        soff[j] = (uint32_t)s << 9;                 // *256 cols *2 B
        toff[j] = ((uint32_t)t << 9) + 256u;        // + D_DIM*2 B
    }

    const char* Pb = (const char*)g_Ph;
    const uint32_t lb = (uint32_t)hl << 4;          // 16 B per lane

    const float4 w0 = *(const float4*)(g_W2p + hl * 8);
    const float4 w1 = *(const float4*)(g_W2p + hl * 8 + 4);

    uint4 av[4], bv[4];
    #pragma unroll
    for (int j = 0; j < 4; ++j) {
        av[j] = *(const uint4*)(Pb + soff[j] + lb);
        bv[j] = *(const uint4*)(Pb + toff[j] + lb);
    }

    const __half2 z = __float2half2_rn(0.f);
    float s[4];
    #pragma unroll
    for (int j = 0; j < 4; ++j) {
        __half2 h0 = __hmax2(__hadd2(*(const __half2*)&av[j].x, *(const __half2*)&bv[j].x), z);
        __half2 h1 = __hmax2(__hadd2(*(const __half2*)&av[j].y, *(const __half2*)&bv[j].y), z);
        __half2 h2 = __hmax2(__hadd2(*(const __half2*)&av[j].z, *(const __half2*)&bv[j].z), z);
        __half2 h3 = __hmax2(__hadd2(*(const __half2*)&av[j].w, *(const __half2*)&bv[j].w), z);
        float2 f0 = __half22float2(h0);
        float2 f1 = __half22float2(h1);
        float2 f2 = __half22float2(h2);
        float2 f3 = __half22float2(h3);
        float r = f0.x * w0.x;
        r = fmaf(f0.y, w0.y, r);
        r = fmaf(f1.x, w0.z, r);
        r = fmaf(f1.y, w0.w, r);
        r = fmaf(f2.x, w1.x, r);
        r = fmaf(f2.y, w1.y, r);
        r = fmaf(f3.x, w1.z, r);
        r = fmaf(f3.y, w1.w, r);
        s[j] = r;
    }

    #pragma unroll
    for (int off = 8; off; off >>= 1) {
        #pragma unroll
        for (int j = 0; j < 4; ++j)
            s[j] += __shfl_xor_sync(0xffffffffu, s[j], off);
    }

    if (hl == 0) {
        const float bb = b2[0];
        #pragma unroll
        for (int j = 0; j < 4; ++j)
            if (e0 + j < Etot) out[e0 + j] = s[j] + bb;
    }
}

// ---------------------------------------------------------------------------
extern "C" void kernel_launch(void* const* d_in, const int* in_sizes, int n_in,
                              void* d_out, int out_size) {
    const float* x   = (const float*)d_in[0];
    const void*  pos = d_in[1];
    const void*  neg = d_in[2];
    const float* W1  = (const float*)d_in[3];
    const float* b1  = (const float*)d_in[4];
    const float* W2  = (const float*)d_in[5];
    const float* b2  = (const float*)d_in[6];
    float* out = (float*)d_out;

    const int M    = in_sizes[0] / D_DIM;
    const int Epos = in_sizes[1] / 2;
    const int Eneg = in_sizes[2] / 2;
    const int Etot = Epos + Eneg;
    const int ntiles = (M + 127) / 128;

    static bool attr_set = false;
    if (!attr_set) {
        cudaFuncSetAttribute(gemm_mma_kernel,
                             cudaFuncAttributeMaxDynamicSharedMemorySize, GEMM_SMEM);
        attr_set = true;
    }

    detect_idx_kernel<<<1, 32>>>((const long long*)pos);
    prep_w_kernel<<<(N_COLS * D_DIM + 255) / 256, 256>>>(W1, W2);
    const int total8 = M * D_DIM / 8;
    prep_x_kernel<<<(total8 + 255) / 256, 256>>>(x, total8);

    dim3 gg((unsigned)ntiles, 2);
    gemm_mma_kernel<<<gg, 256, GEMM_SMEM>>>(b1, M);

    int warps = (Etot + 7) / 8;
    unsigned eblocks = (unsigned)((warps + 7) / 8);
    edge_kernel<<<eblocks, 256>>>((const long long*)pos, (const long long*)neg,
                                  b2, out, Epos, Eneg);
}